// round 7
// baseline (speedup 1.0000x reference)
#include <cuda_runtime.h>

#define NTOK 8192      // B*N
#define DIMQ 256
#define CD   64
#define NK   16384

#define KSPL   32
#define KCH    (NK/KSPL)        // 512 codes per K-chunk
#define KT     64               // codes per staged tile
#define ITERS_U (KCH/KT)        // 8 iterations per unit
#define TTOK   128              // tokens per tile
#define NTILES (NTOK/TTOK)      // 64 token tiles
#define NUNITS (KSPL*NTILES)    // 2048 work units
#define GRID_ARGMIN 304         // 2 CTAs/SM on 152-SM GB300

#define OUT_OFF_IDX  (NTOK*DIMQ)
#define OUT_OFF_LOSS (NTOK*DIMQ + NTOK)

// ---- dynamic smem layout (bytes) ----
#define OFF_E2   0                    // 2 x 64 rows x 512B (dup-e)  = 65536
#define OFF_ZPT  65536                // 64 x 130 floats             = 33280
#define OFF_A    98816                // 128 floats                  = 512
#define OFF_BK   99328                // 512 floats                  = 2048
#define OFF_REDV 101376               // 8 x 128 floats              = 4096
#define OFF_REDI 105472               // 8 x 128 ints                = 4096
#define OFF_USH  109568               // 16
#define SMEM_ARGMIN 109584

// ---- scratch ----
__device__ float g_zp[NTOK*CD];
__device__ float g_A[NTOK];
__device__ float g_Bk[NK];
__device__ float g_mv[KSPL*NTOK];
__device__ int   g_mi[KSPL*NTOK];
__device__ int   g_idx[NTOK];
__device__ float g_part[NTOK];
__device__ int   g_unit;

typedef unsigned long long ull;

__device__ __forceinline__ void ffma2(ull& d, ull a, ull b){
    asm("fma.rn.f32x2 %0, %1, %2, %0;" : "+l"(d) : "l"(a), "l"(b));
}
__device__ __forceinline__ float2 upk(ull v){
    float2 r;
    asm("mov.b64 {%0, %1}, %2;" : "=f"(r.x), "=f"(r.y) : "l"(v));
    return r;
}

// ---------------------------------------------------------------------------
// Kernel 1: zp = z @ Wq^T + bq -- strictly-sequential ascending-d chain
// (bit-matches reference GEMM accumulation; DO NOT reorder)
// ---------------------------------------------------------------------------
__global__ __launch_bounds__(64) void k_zp(const float* __restrict__ z,
                                           const float* __restrict__ Wq,
                                           const float* __restrict__ bq) {
    __shared__ float zrow[DIMQ];
    __shared__ float vsh[CD];
    int t = blockIdx.x;
    int c = threadIdx.x;
    ((float4*)zrow)[c] = ((const float4*)(z + t*DIMQ))[c];
    __syncthreads();
    const float4* w4  = (const float4*)(Wq + c*DIMQ);
    const float4* zr4 = (const float4*)zrow;
    float v = 0.f;
#pragma unroll
    for (int i=0;i<DIMQ/4;i++){
        float4 w = w4[i]; float4 zz = zr4[i];
        v = fmaf(w.x, zz.x, v);
        v = fmaf(w.y, zz.y, v);
        v = fmaf(w.z, zz.z, v);
        v = fmaf(w.w, zz.w, v);
    }
    v = v + bq[c];
    g_zp[t*CD + c] = v;
    vsh[c] = v*v;
    __syncthreads();
    if (c < 32) vsh[c] += vsh[c+32];
    __syncwarp();
    if (c < 32){
        float s = vsh[c];
#pragma unroll
        for (int o=16;o>0;o>>=1) s += __shfl_down_sync(0xffffffffu, s, o);
        if (c==0) g_A[t] = s;
    }
}

// ---------------------------------------------------------------------------
// Kernel 2: B[k] = ||emb_k||^2
// ---------------------------------------------------------------------------
__global__ void k_B(const float* __restrict__ emb){
    int k = blockIdx.x*blockDim.x + threadIdx.x;
    if (k >= NK) return;
    const float4* e4 = (const float4*)(emb + k*CD);
    float s0=0.f,s1=0.f,s2=0.f,s3=0.f;
#pragma unroll
    for (int i=0;i<16;i++){
        float4 e = e4[i];
        s0=fmaf(e.x,e.x,s0); s1=fmaf(e.y,e.y,s1);
        s2=fmaf(e.z,e.z,s2); s3=fmaf(e.w,e.w,s3);
    }
    g_Bk[k] = (s0+s1)+(s2+s3);
}

// ---------------------------------------------------------------------------
// Kernel 2.5: work-queue reset (also positions k_argmin as the 4th launch
// so the fixed-offset ncu capture lands on it)
// ---------------------------------------------------------------------------
__global__ void k_reset(){ if (threadIdx.x==0) g_unit = 0; }

// ---------------------------------------------------------------------------
// Kernel 3: argmin -- persistent CTAs + work queue, packed fp32x2 FMA.
// Unit = (token-tile of 128, K-chunk of 512).  Block: 32 lanes x 4 tokens
// (two f32x2 pairs: tokens {2tg,2tg+1} and {64+2tg,64+2tg+1}) x 8 code-warps
// x 8 codes.  Per 2-c step: 4 zp LDS.64 + 8 e LDS.128 + 32 FFMA2.
// e staged DUPLICATED (v,v): every accumulator lane is a strictly-sequential
// ascending-c scalar fp32 chain -- bit-identical to the reference argmin.
// ---------------------------------------------------------------------------
__global__ __launch_bounds__(256, 2) void k_argmin(const float* __restrict__ emb){
    extern __shared__ char smem[];
    float* e2    = (float*)(smem + OFF_E2);     // [2][KT][128] dup-e
    float* zpT   = (float*)(smem + OFF_ZPT);    // [CD][130]
    float* A_s   = (float*)(smem + OFF_A);      // [128]
    float* Bk_s  = (float*)(smem + OFF_BK);     // [KCH]
    float* red_v = (float*)(smem + OFF_REDV);   // [8][128]
    int*   red_i = (int*)  (smem + OFF_REDI);
    int*   u_sh  = (int*)  (smem + OFF_USH);

    int tid = threadIdx.x;
    int tg  = tid & 31;               // token-lane
    int kg  = tid >> 5;               // code-warp

    const float4* e4 = (const float4*)emb;

    for (;;){
        if (tid == 0) u_sh[0] = atomicAdd(&g_unit, 1);
        __syncthreads();
        int u = u_sh[0];
        if (u >= NUNITS) break;
        int chunk = u >> 6;           // consecutive units share chunk (L2 reuse)
        int tile  = u & 63;
        int t0    = tile * TTOK;
        int kb0   = chunk * KCH;

        // ---- stage zpT (c-major), A, Bk chunk; prefetch e tile 0 ----
#pragma unroll
        for (int i=0;i<32;i++){
            int lin = tid + 256*i;    // 0..8191
            int r = lin >> 6, c = lin & 63;
            zpT[c*130 + r] = g_zp[(t0+r)*CD + c];
        }
        if (tid < 128){
            A_s[tid] = g_A[t0+tid];
            ((float4*)Bk_s)[tid] = ((const float4*)(g_Bk + kb0))[tid];
        }

        float4 pf[4];
#pragma unroll
        for (int i=0;i<4;i++) pf[i] = e4[(kb0<<4) + tid + 256*i];

        __syncthreads();
        {
            float* eb = e2;           // buf 0
#pragma unroll
            for (int i=0;i<4;i++){
                int lin = tid + 256*i;
                int kk = lin >> 4, c4 = lin & 15;
                float4 v = pf[i];
                float* row = eb + kk*128 + c4*8;
                ((float4*)row)[0] = make_float4(v.x,v.x,v.y,v.y);
                ((float4*)row)[1] = make_float4(v.z,v.z,v.w,v.w);
            }
        }

        float bv00 = 3.402823466e38f, bv01 = 3.402823466e38f;
        float bv10 = 3.402823466e38f, bv11 = 3.402823466e38f;
        int   bi00 = 0, bi01 = 0, bi10 = 0, bi11 = 0;
        int buf = 0;

        for (int it=0; it<ITERS_U; it++){
            if (it+1 < ITERS_U){
                int kb4 = (kb0 + (it+1)*KT) << 4;
#pragma unroll
                for (int i=0;i<4;i++) pf[i] = e4[kb4 + tid + 256*i];
            }
            __syncthreads();
            if (it+1 < ITERS_U){
                float* eb = e2 + (buf^1)*(KT*128);
#pragma unroll
                for (int i=0;i<4;i++){
                    int lin = tid + 256*i;
                    int kk = lin >> 4, c4 = lin & 15;
                    float4 v = pf[i];
                    float* row = eb + kk*128 + c4*8;
                    ((float4*)row)[0] = make_float4(v.x,v.x,v.y,v.y);
                    ((float4*)row)[1] = make_float4(v.z,v.z,v.w,v.w);
                }
            }

            // ---- compute: 4 tokens x 8 codes, packed f32x2 ----
            ull acc0[8], acc1[8];
#pragma unroll
            for (int j=0;j<8;j++){ acc0[j]=0ull; acc1[j]=0ull; }

            const ull*  Z  = (const ull*)zpT;                 // 65 ull per c-row
            const char* eb = (const char*)(e2 + buf*(KT*128)) + (kg*8)*512;
#pragma unroll 4
            for (int s=0; s<32; s++){                         // 2 c per step
                ull za0 = Z[(2*s  )*65 + tg];
                ull zb0 = Z[(2*s+1)*65 + tg];
                ull za1 = Z[(2*s  )*65 + 32 + tg];
                ull zb1 = Z[(2*s+1)*65 + 32 + tg];
#pragma unroll
                for (int j=0;j<8;j++){
                    ulonglong2 e = *(const ulonglong2*)(eb + j*512 + s*16);
                    ffma2(acc0[j], za0, e.x);
                    ffma2(acc0[j], zb0, e.y);
                    ffma2(acc1[j], za1, e.x);
                    ffma2(acc1[j], zb1, e.y);
                }
            }

            int kb = kb0 + it*KT;
            float a00 = A_s[2*tg], a01 = A_s[2*tg+1];
            float a10 = A_s[64+2*tg], a11 = A_s[65+2*tg];
#pragma unroll
            for (int j=0;j<8;j++){
                float2 p0 = upk(acc0[j]);
                float2 p1 = upk(acc1[j]);
                float Bk = Bk_s[it*KT + kg*8 + j];
                int k = kb + kg*8 + j;
                float s00 = (a00 + Bk) - 2.0f*p0.x;   // reference rounding
                float s01 = (a01 + Bk) - 2.0f*p0.y;
                float s10 = (a10 + Bk) - 2.0f*p1.x;
                float s11 = (a11 + Bk) - 2.0f*p1.y;
                if (s00 < bv00){ bv00 = s00; bi00 = k; }  // strict < == first idx
                if (s01 < bv01){ bv01 = s01; bi01 = k; }
                if (s10 < bv10){ bv10 = s10; bi10 = k; }
                if (s11 < bv11){ bv11 = s11; bi11 = k; }
            }
            buf ^= 1;
        }

        // ---- reduce across code-warps ----
        red_v[kg*128 + 2*tg]      = bv00; red_v[kg*128 + 2*tg+1]    = bv01;
        red_v[kg*128 + 64 + 2*tg] = bv10; red_v[kg*128 + 65 + 2*tg] = bv11;
        red_i[kg*128 + 2*tg]      = bi00; red_i[kg*128 + 2*tg+1]    = bi01;
        red_i[kg*128 + 64 + 2*tg] = bi10; red_i[kg*128 + 65 + 2*tg] = bi11;
        __syncthreads();
        if (tid < 128){
            float bv = red_v[tid]; int bi = red_i[tid];
#pragma unroll
            for (int g=1; g<8; g++){
                float v = red_v[g*128 + tid]; int i2 = red_i[g*128 + tid];
                if (v < bv || (v == bv && i2 < bi)){ bv = v; bi = i2; }
            }
            g_mv[chunk*NTOK + t0 + tid] = bv;
            g_mi[chunk*NTOK + t0 + tid] = bi;
        }
    }
}

// ---------------------------------------------------------------------------
// Kernel 4: combine K-chunks (ascending chunk order preserves first-index)
// ---------------------------------------------------------------------------
__global__ void k_combine(float* __restrict__ d_out, int out_size){
    int t = blockIdx.x*blockDim.x + threadIdx.x;
    if (t >= NTOK) return;
    float bv = g_mv[t]; int bi = g_mi[t];
#pragma unroll
    for (int s=1;s<KSPL;s++){
        float v = g_mv[s*NTOK+t]; int i2 = g_mi[s*NTOK+t];
        if (v < bv || (v == bv && i2 < bi)){ bv = v; bi = i2; }
    }
    g_idx[t] = bi;
    if (out_size > OUT_OFF_IDX + t) d_out[OUT_OFF_IDX + t] = (float)bi;
}

// ---------------------------------------------------------------------------
// Kernel 5: out = emb[idx] @ Wp^T + bp  + per-token commit-loss partial
// ---------------------------------------------------------------------------
__global__ __launch_bounds__(256) void k_out(const float* __restrict__ emb,
                                             const float* __restrict__ Wp,
                                             const float* __restrict__ bp,
                                             float* __restrict__ d_out){
    __shared__ float er[CD];
    __shared__ float red[CD];
    int t = blockIdx.x;
    int d = threadIdx.x;
    int idx = g_idx[t];
    if (d < CD){
        float ev = emb[idx*CD + d];
        er[d] = ev;
        float df = ev - g_zp[t*CD + d];
        red[d] = df*df;
    }
    __syncthreads();
    const float4* w4  = (const float4*)(Wp + d*CD);
    const float4* er4 = (const float4*)er;
    float a0=0.f,a1=0.f,a2=0.f,a3=0.f;
#pragma unroll
    for (int i=0;i<16;i++){
        float4 w = w4[i]; float4 e = er4[i];
        a0=fmaf(w.x,e.x,a0); a1=fmaf(w.y,e.y,a1);
        a2=fmaf(w.z,e.z,a2); a3=fmaf(w.w,e.w,a3);
    }
    d_out[t*DIMQ + d] = (a0+a1)+(a2+a3) + bp[d];
    if (d < 32) red[d] += red[d+32];
    __syncwarp();
    if (d < 32){
        float s = red[d];
#pragma unroll
        for (int o=16;o>0;o>>=1) s += __shfl_down_sync(0xffffffffu, s, o);
        if (d==0) g_part[t] = s;
    }
}

// ---------------------------------------------------------------------------
// Kernel 6: loss = m*(1+BETA)
// ---------------------------------------------------------------------------
__global__ void k_loss(float* __restrict__ d_out, int out_size){
    __shared__ float sh[256];
    int tid = threadIdx.x;
    float s = 0.f;
    for (int i=tid;i<NTOK;i+=256) s += g_part[i];
    sh[tid] = s;
    __syncthreads();
    for (int o=128;o>0;o>>=1){
        if (tid < o) sh[tid] += sh[tid+o];
        __syncthreads();
    }
    if (tid==0 && out_size > OUT_OFF_LOSS){
        float m = sh[0] / (float)(NTOK*CD);
        d_out[OUT_OFF_LOSS] = m + 0.25f*m;
    }
}

// ---------------------------------------------------------------------------
extern "C" void kernel_launch(void* const* d_in, const int* in_sizes, int n_in,
                              void* d_out, int out_size){
    const float* z   = (const float*)d_in[0];
    const float* Wq  = (const float*)d_in[1];
    const float* bq  = (const float*)d_in[2];
    const float* emb = (const float*)d_in[3];
    const float* Wp  = (const float*)d_in[4];
    const float* bp  = (const float*)d_in[5];
    float* out = (float*)d_out;
    (void)in_sizes; (void)n_in;

    static int attr_done = 0;
    if (!attr_done){
        cudaFuncSetAttribute(k_argmin, cudaFuncAttributeMaxDynamicSharedMemorySize,
                             SMEM_ARGMIN);
        attr_done = 1;
    }

    k_zp<<<NTOK, 64>>>(z, Wq, bq);          // launch 0
    k_B<<<NK/256, 256>>>(emb);              // launch 1
    k_reset<<<1, 32>>>();                   // launch 2
    k_argmin<<<GRID_ARGMIN, 256, SMEM_ARGMIN>>>(emb);   // launch 3 (profiled)
    k_combine<<<NTOK/256, 256>>>(out, out_size);
    k_out<<<NTOK, 256>>>(emb, Wp, bp, out);
    k_loss<<<1, 256>>>(out, out_size);
}

// round 8
// speedup vs baseline: 1.4559x; 1.4559x over previous
#include <cuda_runtime.h>

#define NTOK 8192
#define DIMQ 256
#define CD   64
#define NK   16384

#define KSPL   32
#define KCH    512              // codes per work unit
#define KT     128              // codes per staged tile
#define IT_U   (KCH/KT)         // 4
#define TTOK   128              // tokens per tile
#define NTILES (NTOK/TTOK)      // 64
#define NUNITS (NTILES*KSPL)    // 2048
#define GRID_AM 152

#define OUT_OFF_IDX  (NTOK*DIMQ)
#define OUT_OFF_LOSS (NTOK*DIMQ + NTOK)

// ---- k_argmin smem (bytes) ----
#define ROW_Z 1152              // 128 dup-tokens*8B + pad16 per 16 tokens
#define ROW_E 560               // 2 halves*272 (+pad per 4 cg) + 16
#define EBUF  (64*ROW_E)        // 35840
#define OFF_ZD  0               // 64*1152 = 73728
#define OFF_E   73728           // 2*35840 = 71680
#define OFF_BKS 145408          // 2048
#define OFF_RV  147456          // 16*128*4 = 8192
#define OFF_RI  155648          // 8192
#define OFF_USH 163840          // 16
#define SMEM_AM 163856

// ---- k_zp smem ----
#define ZROW 1040               // 256 floats + 16B pad
#define SMEM_ZP (64*ZROW*2)     // Wq 64 rows + z 64 tokens = 133120

// ---- k_out smem ----
#define WPROW 272               // 64 floats + 16B pad
#define SMEM_KO (256*WPROW + 128*WPROW)   // 69632 + 34816 = 104448

// ---- scratch ----
__device__ float g_zp[NTOK*CD];
__device__ float g_A[NTOK];
__device__ float g_Bk[NK];
__device__ float g_mv[KSPL*NTOK];
__device__ int   g_mi[KSPL*NTOK];
__device__ int   g_idx[NTOK];
__device__ float g_part[NTOK];
__device__ int   g_unit;

typedef unsigned long long ull;

__device__ __forceinline__ void ffma2(ull& d, ull a, ull b){
    asm("fma.rn.f32x2 %0, %1, %2, %0;" : "+l"(d) : "l"(a), "l"(b));
}
__device__ __forceinline__ ull fma2v(ull a, ull b, ull c){
    ull d; asm("fma.rn.f32x2 %0, %1, %2, %3;" : "=l"(d) : "l"(a), "l"(b), "l"(c));
    return d;
}
__device__ __forceinline__ ull add2(ull a, ull b){
    ull d; asm("add.rn.f32x2 %0, %1, %2;" : "=l"(d) : "l"(a), "l"(b));
    return d;
}
__device__ __forceinline__ ull dup2(float f){
    ull d; asm("mov.b64 %0, {%1, %1};" : "=l"(d) : "f"(f)); return d;
}
__device__ __forceinline__ float2 upk(ull v){
    float2 r; asm("mov.b64 {%0, %1}, %2;" : "=f"(r.x), "=f"(r.y) : "l"(v));
    return r;
}

// ---------------------------------------------------------------------------
// Kernel 1: zp = z @ Wq^T + bq.  128 blocks x 64 tokens, Wq + z staged in smem.
// Per-(t,c) chain: strictly-sequential ascending-d (.x,.y,.z,.w over ascending
// float4) -- identical to the passing version.  A-tree identical too.
// ---------------------------------------------------------------------------
__global__ __launch_bounds__(256) void k_zp(const float* __restrict__ z,
                                            const float* __restrict__ Wq,
                                            const float* __restrict__ bq){
    extern __shared__ char sm[];
    char* wsm = sm;                 // Wq rows
    char* zsm = sm + 64*ZROW;       // z rows / later v^2
    int tid = threadIdx.x;
    int ts = tid >> 6, c = tid & 63;
    int t0 = blockIdx.x * 64;

    const float4* wq4 = (const float4*)Wq;
    const float4* z4  = (const float4*)z;
#pragma unroll
    for (int i=0;i<16;i++){
        int lin = tid + 256*i;                  // 0..4095
        int r = lin >> 6, q = lin & 63;
        *(float4*)(wsm + r*ZROW + q*16) = wq4[r*64 + q];
        *(float4*)(zsm + r*ZROW + q*16) = z4[(t0+r)*64 + q];
    }
    __syncthreads();

    float acc[16];
#pragma unroll
    for (int i=0;i<16;i++) acc[i] = 0.f;
#pragma unroll 4
    for (int k4=0;k4<64;k4++){
        float4 w = *(const float4*)(wsm + c*ZROW + k4*16);
#pragma unroll
        for (int i=0;i<16;i++){
            float4 zz = *(const float4*)(zsm + (ts*16+i)*ZROW + k4*16);
            acc[i] = fmaf(w.x, zz.x, acc[i]);
            acc[i] = fmaf(w.y, zz.y, acc[i]);
            acc[i] = fmaf(w.z, zz.z, acc[i]);
            acc[i] = fmaf(w.w, zz.w, acc[i]);
        }
    }
    float bqc = bq[c];
    float vv[16];
#pragma unroll
    for (int i=0;i<16;i++){
        float v = acc[i] + bqc;
        g_zp[(t0 + ts*16 + i)*CD + c] = v;
        vv[i] = v*v;
    }
    __syncthreads();                 // z data consumed; reuse zsm for v^2
#pragma unroll
    for (int i=0;i<16;i++)
        *(float*)(zsm + (ts*16+i)*ZROW + c*4) = vv[i];
    __syncthreads();
    // A-tree: s = v2[l] + v2[l+32], then shfl_down 16,8,4,2,1 (bit-matches)
    int l = tid & 31, w = tid >> 5;
#pragma unroll
    for (int tt=0;tt<8;tt++){
        int t = w*8 + tt;
        float s = *(float*)(zsm + t*ZROW + l*4) + *(float*)(zsm + t*ZROW + (l+32)*4);
        s += __shfl_down_sync(0xffffffffu, s, 16);
        s += __shfl_down_sync(0xffffffffu, s, 8);
        s += __shfl_down_sync(0xffffffffu, s, 4);
        s += __shfl_down_sync(0xffffffffu, s, 2);
        s += __shfl_down_sync(0xffffffffu, s, 1);
        if (l==0) g_A[t0+t] = s;
    }
}

// ---------------------------------------------------------------------------
// Kernel 2: B[k] = ||emb_k||^2  (value absorbed by fl(A+B); order free)
// ---------------------------------------------------------------------------
__global__ void k_B(const float* __restrict__ emb){
    int k = blockIdx.x*blockDim.x + threadIdx.x;
    if (k >= NK) return;
    const float4* e4 = (const float4*)(emb + k*CD);
    float s0=0.f,s1=0.f,s2=0.f,s3=0.f;
#pragma unroll
    for (int i=0;i<16;i++){
        float4 e = e4[i];
        s0=fmaf(e.x,e.x,s0); s1=fmaf(e.y,e.y,s1);
        s2=fmaf(e.z,e.z,s2); s3=fmaf(e.w,e.w,s3);
    }
    g_Bk[k] = (s0+s1)+(s2+s3);
}

__global__ void k_reset(){ if (threadIdx.x==0) g_unit = 0; }

// ---------------------------------------------------------------------------
// Kernel 3: argmin.  152 persistent CTAs, tile-major queue (unit = tile*32+chunk).
// Warps: 4 token-rows x 2 code-cols.  Lanes: 4 token-groups x 8 code-groups.
// Thread: 8 tokens x 8 codes; acc packed over CODE pairs (32 f32x2 accs).
// zp staged dup (v,v) per tile; e staged c-major non-dup per chunk tile.
// Score = fma2(acc, -2, add2(A,B)) == reference fl(fl(A+B)-fl(2*acc)) bitwise.
// ---------------------------------------------------------------------------
__global__ __launch_bounds__(256, 1) void k_argmin(const float* __restrict__ emb){
    extern __shared__ char sm[];
    char*  zd  = sm + OFF_ZD;
    char*  es  = sm + OFF_E;
    float* bks = (float*)(sm + OFF_BKS);
    float* rv  = (float*)(sm + OFF_RV);
    int*   ri  = (int*)  (sm + OFF_RI);
    int*   ush = (int*)  (sm + OFF_USH);

    int tid  = threadIdx.x;
    int lane = tid & 31, wid = tid >> 5;
    int wr = wid & 3, wc = wid >> 2;          // 4 token-rows x 2 code-cols
    int tg4 = lane >> 3, cg = lane & 7;       // 4 token-grps x 8 code-grps
    // staging ids: lanes 0-15 = consecutive c4 (coalesced gmem), kq = code octet
    int c4s = tid & 15, kq = tid >> 4;        // kq 0..15 -> codes kq*8..+7
    int koffB = (kq>>3)*272 + (kq&7)*32 + (((kq&7)>>2)<<4);
    int zoff  = wr*288 + tg4*64 + ((tg4>>1)<<4);
    int eoff  = wc*272 + cg*32 + ((cg>>2)<<4);

    const float4* e4  = (const float4*)emb;
    const float4* zp4 = (const float4*)g_zp;
    const ull NEG2 = 0xC0000000C0000000ULL;
    int last_tile = -1;
    ull a_dup[8];

    for(;;){
        if (tid==0) ush[0] = atomicAdd(&g_unit, 1);
        __syncthreads();
        int u = ush[0];
        if (u >= NUNITS) break;
        int tile = u >> 5, chunk = u & 31;
        int t0 = tile*TTOK, kb0 = chunk*KCH;

        if (tile != last_tile){
            last_tile = tile;
            // stage zp duplicated: rows c, token t at tpos(t)=t*8+(t>>4)*16
#pragma unroll
            for (int i=0;i<8;i++){
                int lin = tid + 256*i;          // 0..2047 float4s
                int t = lin >> 4, c4 = lin & 15;
                float4 v = zp4[(t0+t)*16 + c4];
                char* base = zd + t*8 + ((t>>4)<<4);
                *(ull*)(base + (4*c4+0)*ROW_Z) = dup2(v.x);
                *(ull*)(base + (4*c4+1)*ROW_Z) = dup2(v.y);
                *(ull*)(base + (4*c4+2)*ROW_Z) = dup2(v.z);
                *(ull*)(base + (4*c4+3)*ROW_Z) = dup2(v.w);
            }
            int tbase = t0 + wr*32 + tg4*8;
#pragma unroll
            for (int tp=0;tp<8;tp++) a_dup[tp] = dup2(g_A[tbase+tp]);
        }
        if (tid < 128) ((float4*)bks)[tid] = ((const float4*)(g_Bk + kb0))[tid];

        float4 pf[8];
#define LOADE(ITT) { int kb = kb0 + (ITT)*KT + kq*8;                        \
        _Pragma("unroll")                                                   \
        for (int j=0;j<8;j++) pf[j] = e4[(kb+j)*16 + c4s]; }
#define STOREE(BUFP) { char* eb = es + (BUFP)*EBUF + koffB;                 \
        _Pragma("unroll")                                                   \
        for (int r=0;r<4;r++){                                              \
            float4 w0 = make_float4(((float*)&pf[0])[r], ((float*)&pf[1])[r],\
                                    ((float*)&pf[2])[r], ((float*)&pf[3])[r]);\
            float4 w1 = make_float4(((float*)&pf[4])[r], ((float*)&pf[5])[r],\
                                    ((float*)&pf[6])[r], ((float*)&pf[7])[r]);\
            *(float4*)(eb + (4*c4s+r)*ROW_E)      = w0;                     \
            *(float4*)(eb + (4*c4s+r)*ROW_E + 16) = w1; } }

        LOADE(0);
        __syncthreads();               // zd + bks visible
        STOREE(0);

        float bv[8]; int bi[8];
#pragma unroll
        for (int tp=0;tp<8;tp++){ bv[tp] = 3.402823466e38f; bi[tp] = 0; }
        int buf = 0;

        for (int it=0; it<IT_U; it++){
            if (it+1 < IT_U) LOADE(it+1);
            __syncthreads();           // current buf stores visible
            if (it+1 < IT_U) STOREE(buf^1);

            ull acc[8][4];
#pragma unroll
            for (int tp=0;tp<8;tp++)
#pragma unroll
                for (int jp=0;jp<4;jp++) acc[tp][jp] = 0ull;

            const char* zrow = zd + zoff;
            const char* erow = es + buf*EBUF + eoff;
#pragma unroll 4
            for (int c=0;c<64;c++){
                ulonglong2 zA = *(const ulonglong2*)(zrow + c*ROW_Z);
                ulonglong2 zB = *(const ulonglong2*)(zrow + c*ROW_Z + 16);
                ulonglong2 zC = *(const ulonglong2*)(zrow + c*ROW_Z + 32);
                ulonglong2 zD = *(const ulonglong2*)(zrow + c*ROW_Z + 48);
                ulonglong2 eA = *(const ulonglong2*)(erow + c*ROW_E);
                ulonglong2 eB = *(const ulonglong2*)(erow + c*ROW_E + 16);
                ffma2(acc[0][0], zA.x, eA.x); ffma2(acc[0][1], zA.x, eA.y);
                ffma2(acc[0][2], zA.x, eB.x); ffma2(acc[0][3], zA.x, eB.y);
                ffma2(acc[1][0], zA.y, eA.x); ffma2(acc[1][1], zA.y, eA.y);
                ffma2(acc[1][2], zA.y, eB.x); ffma2(acc[1][3], zA.y, eB.y);
                ffma2(acc[2][0], zB.x, eA.x); ffma2(acc[2][1], zB.x, eA.y);
                ffma2(acc[2][2], zB.x, eB.x); ffma2(acc[2][3], zB.x, eB.y);
                ffma2(acc[3][0], zB.y, eA.x); ffma2(acc[3][1], zB.y, eA.y);
                ffma2(acc[3][2], zB.y, eB.x); ffma2(acc[3][3], zB.y, eB.y);
                ffma2(acc[4][0], zC.x, eA.x); ffma2(acc[4][1], zC.x, eA.y);
                ffma2(acc[4][2], zC.x, eB.x); ffma2(acc[4][3], zC.x, eB.y);
                ffma2(acc[5][0], zC.y, eA.x); ffma2(acc[5][1], zC.y, eA.y);
                ffma2(acc[5][2], zC.y, eB.x); ffma2(acc[5][3], zC.y, eB.y);
                ffma2(acc[6][0], zD.x, eA.x); ffma2(acc[6][1], zD.x, eA.y);
                ffma2(acc[6][2], zD.x, eB.x); ffma2(acc[6][3], zD.x, eB.y);
                ffma2(acc[7][0], zD.y, eA.x); ffma2(acc[7][1], zD.y, eA.y);
                ffma2(acc[7][2], zD.y, eB.x); ffma2(acc[7][3], zD.y, eB.y);
            }

            int kloc = it*KT + wc*64 + cg*8;     // code offset within chunk
            int kbase = kb0 + kloc;
            const ull* bk2 = (const ull*)bks + (kloc >> 1);
            ull bkp[4];
            { ulonglong2 b01 = *(const ulonglong2*)bk2;
              ulonglong2 b23 = *(const ulonglong2*)(bk2+2);
              bkp[0]=b01.x; bkp[1]=b01.y; bkp[2]=b23.x; bkp[3]=b23.y; }
#pragma unroll
            for (int tp=0;tp<8;tp++){
#pragma unroll
                for (int jp=0;jp<4;jp++){
                    ull ab = add2(a_dup[tp], bkp[jp]);     // fl(A+B) per lane
                    ull s2 = fma2v(acc[tp][jp], NEG2, ab); // fl(ab - 2*acc)
                    float2 s = upk(s2);
                    int k0 = kbase + 2*jp;
                    if (s.x < bv[tp]){ bv[tp] = s.x; bi[tp] = k0;   }
                    if (s.y < bv[tp]){ bv[tp] = s.y; bi[tp] = k0+1; }
                }
            }
            buf ^= 1;
        }

        // per-token reduction across the 16 (wc,cg) code-threads
        int row = wc*8 + cg;
        int tcol = wr*32 + tg4*8;
#pragma unroll
        for (int tp=0;tp<8;tp++){
            rv[row*128 + tcol+tp] = bv[tp];
            ri[row*128 + tcol+tp] = bi[tp];
        }
        __syncthreads();
        if (tid < 128){
            float b = rv[tid]; int bidx = ri[tid];
#pragma unroll
            for (int g=1; g<16; g++){
                float v = rv[g*128 + tid]; int i2 = ri[g*128 + tid];
                if (v < b || (v == b && i2 < bidx)){ b = v; bidx = i2; }
            }
            g_mv[chunk*NTOK + t0 + tid] = b;
            g_mi[chunk*NTOK + t0 + tid] = bidx;
        }
    }
#undef LOADE
#undef STOREE
}

// ---------------------------------------------------------------------------
// Kernel 4: combine K-chunks (order-independent tie rule)
// ---------------------------------------------------------------------------
__global__ void k_combine(float* __restrict__ d_out, int out_size){
    int t = blockIdx.x*blockDim.x + threadIdx.x;
    if (t >= NTOK) return;
    float bv = g_mv[t]; int bi = g_mi[t];
#pragma unroll
    for (int s=1;s<KSPL;s++){
        float v = g_mv[s*NTOK+t]; int i2 = g_mi[s*NTOK+t];
        if (v < bv || (v == bv && i2 < bi)){ bv = v; bi = i2; }
    }
    g_idx[t] = bi;
    if (out_size > OUT_OFF_IDX + t) d_out[OUT_OFF_IDX + t] = (float)bi;
}

// ---------------------------------------------------------------------------
// Kernel 5: out = emb[idx] @ Wp^T + bp.  64 blocks x 128 tokens.
// Wp staged in smem; gathered e staged in smem; Wp row held in registers.
// Also per-token commit-loss partial.
// ---------------------------------------------------------------------------
__global__ __launch_bounds__(256) void k_out(const float* __restrict__ emb,
                                             const float* __restrict__ Wp,
                                             const float* __restrict__ bp,
                                             float* __restrict__ d_out){
    extern __shared__ char sm[];
    char* wsm = sm;                    // 256 rows x 272
    char* esm = sm + 256*WPROW;        // 128 tokens x 272
    int tid = threadIdx.x;
    int t0 = blockIdx.x * 128;

    const float4* wp4 = (const float4*)Wp;
    const float4* em4 = (const float4*)emb;
#pragma unroll
    for (int i=0;i<16;i++){
        int lin = tid + 256*i;                  // 0..4095
        int d = lin >> 4, c4 = lin & 15;
        *(float4*)(wsm + d*WPROW + c4*16) = wp4[d*16 + c4];
    }
#pragma unroll
    for (int i=0;i<8;i++){
        int lin = tid + 256*i;                  // 0..2047
        int t = lin >> 4, c4 = lin & 15;
        int idx = g_idx[t0+t];
        *(float4*)(esm + t*WPROW + c4*16) = em4[idx*16 + c4];
    }
    __syncthreads();

    // commit-loss partial per token (order within token: sequential over c)
    if (tid < 128){
        int t = tid;
        const float4* zq = (const float4*)(g_zp + (t0+t)*CD);
        float s = 0.f;
#pragma unroll
        for (int c4=0;c4<16;c4++){
            float4 e = *(const float4*)(esm + t*WPROW + c4*16);
            float4 zz = zq[c4];
            float d0 = e.x - zz.x, d1 = e.y - zz.y;
            float d2 = e.z - zz.z, d3 = e.w - zz.w;
            s = fmaf(d0,d0,s); s = fmaf(d1,d1,s);
            s = fmaf(d2,d2,s); s = fmaf(d3,d3,s);
        }
        g_part[t0+t] = s;
    }

    // GEMM: thread = output dim d; Wp row in registers
    float w[64];
#pragma unroll
    for (int c4=0;c4<16;c4++){
        float4 ww = *(const float4*)(wsm + tid*WPROW + c4*16);
        w[4*c4+0]=ww.x; w[4*c4+1]=ww.y; w[4*c4+2]=ww.z; w[4*c4+3]=ww.w;
    }
    float bpv = bp[tid];
    for (int t=0;t<128;t++){
        float a0=0.f,a1=0.f,a2=0.f,a3=0.f;
#pragma unroll
        for (int c4=0;c4<16;c4++){
            float4 e = *(const float4*)(esm + t*WPROW + c4*16);
            a0 = fmaf(w[4*c4+0], e.x, a0);
            a1 = fmaf(w[4*c4+1], e.y, a1);
            a2 = fmaf(w[4*c4+2], e.z, a2);
            a3 = fmaf(w[4*c4+3], e.w, a3);
        }
        d_out[(t0+t)*DIMQ + tid] = (a0+a1)+(a2+a3) + bpv;
    }
}

// ---------------------------------------------------------------------------
// Kernel 6: loss = m*(1+BETA)
// ---------------------------------------------------------------------------
__global__ void k_loss(float* __restrict__ d_out, int out_size){
    __shared__ float sh[256];
    int tid = threadIdx.x;
    float s = 0.f;
    for (int i=tid;i<NTOK;i+=256) s += g_part[i];
    sh[tid] = s;
    __syncthreads();
    for (int o=128;o>0;o>>=1){
        if (tid < o) sh[tid] += sh[tid+o];
        __syncthreads();
    }
    if (tid==0 && out_size > OUT_OFF_LOSS){
        float m = sh[0] / (float)(NTOK*CD);
        d_out[OUT_OFF_LOSS] = m + 0.25f*m;
    }
}

// ---------------------------------------------------------------------------
extern "C" void kernel_launch(void* const* d_in, const int* in_sizes, int n_in,
                              void* d_out, int out_size){
    const float* z   = (const float*)d_in[0];
    const float* Wq  = (const float*)d_in[1];
    const float* bq  = (const float*)d_in[2];
    const float* emb = (const float*)d_in[3];
    const float* Wp  = (const float*)d_in[4];
    const float* bp  = (const float*)d_in[5];
    float* out = (float*)d_out;
    (void)in_sizes; (void)n_in;

    static int attr_done = 0;
    if (!attr_done){
        cudaFuncSetAttribute(k_argmin, cudaFuncAttributeMaxDynamicSharedMemorySize, SMEM_AM);
        cudaFuncSetAttribute(k_zp,     cudaFuncAttributeMaxDynamicSharedMemorySize, SMEM_ZP);
        cudaFuncSetAttribute(k_out,    cudaFuncAttributeMaxDynamicSharedMemorySize, SMEM_KO);
        attr_done = 1;
    }

    k_zp<<<NTOK/64, 256, SMEM_ZP>>>(z, Wq, bq);        // launch 0
    k_B<<<NK/256, 256>>>(emb);                         // launch 1
    k_reset<<<1, 32>>>();                              // launch 2
    k_argmin<<<GRID_AM, 256, SMEM_AM>>>(emb);          // launch 3 (profiled)
    k_combine<<<NTOK/256, 256>>>(out, out_size);
    k_out<<<NTOK/128, 256, SMEM_KO>>>(emb, Wp, bp, out);
    k_loss<<<1, 256>>>(out, out_size);
}